// round 12
// baseline (speedup 1.0000x reference)
#include <cuda_runtime.h>
#include <cstdint>

// Problem constants
#define NN    10000
#define EMB   10
#define EE    160000
#define ERB   200          // edge-reduction blocks
#define RB    16           // rows per big-pass block (2 per lane)
#define BIGB  (NN / RB)    // 625 big-pass blocks
#define NCH   625          // 16-float chunks per row (10000/16)

// ---------------- device scratch (no allocations allowed) ----------------
__device__ float g_xp_a[NN * EMB];        // packed X' ping  (plane-k, j-pair float2)
__device__ float g_xp_b[NN * EMB];        // packed X' pong
__device__ float g_edge_part[ERB * EMB];
__device__ float g_cs_part[BIGB * EMB];
__device__ float g_cvec[EMB];             // ws_b + v_weights + wnp_b
__device__ float g_u[EMB];                // wqact_w @ wqr2
__device__ float g_wv1[EMB];              // wqa_w @ wqr1
__device__ float g_cconst;
__device__ float g_c0;

// packed f32x2 FMA (sm_100+): acc.{lo,hi} += a.{lo,hi} * b.{lo,hi}
#define FMA2(acc, a, b) \
    asm("fma.rn.f32x2 %0, %1, %2, %0;" : "+l"(acc) : "l"(a), "l"(b))

__device__ __forceinline__ float lo32(unsigned long long v) {
    return __uint_as_float((unsigned int)v);
}
__device__ __forceinline__ float hi32(unsigned long long v) {
    return __uint_as_float((unsigned int)(v >> 32));
}

// ---------------- K1: edge embedding partial reduction ----------------
__global__ void edge_reduce_kernel(const float* __restrict__ w,
                                   const float* __restrict__ wew_w,
                                   const float* __restrict__ wew_b) {
    float a[EMB], b[EMB], s[EMB];
#pragma unroll
    for (int k = 0; k < EMB; k++) { a[k] = wew_w[k]; b[k] = wew_b[k]; s[k] = 0.f; }

    for (int e = blockIdx.x * blockDim.x + threadIdx.x; e < EE;
         e += gridDim.x * blockDim.x) {
        float we = w[e];
#pragma unroll
        for (int k = 0; k < EMB; k++)
            s[k] += fmaxf(fmaf(we, a[k], b[k]), 0.f);
    }
#pragma unroll
    for (int k = 0; k < EMB; k++)
        for (int off = 16; off; off >>= 1)
            s[k] += __shfl_down_sync(0xffffffffu, s[k], off);

    __shared__ float red[8 * EMB];
    int t = threadIdx.x, lane = t & 31, wrp = t >> 5;
    if (lane == 0) {
#pragma unroll
        for (int k = 0; k < EMB; k++) red[wrp * EMB + k] = s[k];
    }
    __syncthreads();
    if (t < EMB) {
        float tot = 0.f;
#pragma unroll
        for (int ww = 0; ww < 8; ww++) tot += red[ww * EMB + t];
        g_edge_part[blockIdx.x * EMB + t] = tot;
    }
}

// ---------------- K2: finalize small vectors ----------------
__global__ void finalize_small_kernel(const float* __restrict__ ws_b,
                                      const float* __restrict__ wnw_w,
                                      const float* __restrict__ wnw_b,
                                      const float* __restrict__ wnp_b,
                                      const float* __restrict__ wqr_w,
                                      const float* __restrict__ wqr_b,
                                      const float* __restrict__ wqa_w,
                                      const float* __restrict__ wqa_b,
                                      const float* __restrict__ wqact_w,
                                      const float* __restrict__ wqact_b) {
    __shared__ float s[EMB];
    int t = threadIdx.x;
    if (t < EMB) {
        float acc = 0.f;
        for (int b2 = 0; b2 < ERB; b2++) acc += g_edge_part[b2 * EMB + t];
        s[t] = acc;
    }
    __syncthreads();
    if (t < EMB) {
        float vw = wnw_b[t];
#pragma unroll
        for (int m = 0; m < EMB; m++) vw = fmaf(s[m], wnw_w[m * EMB + t], vw);
        g_cvec[t] = ws_b[t] + vw + wnp_b[t];

        float u = 0.f, v1 = 0.f;
#pragma unroll
        for (int k = 0; k < EMB; k++) {
            u  = fmaf(wqact_w[t * EMB + k], wqr_w[EMB + k], u);
            v1 = fmaf(wqa_w[t * EMB + k],   wqr_w[k],       v1);
        }
        g_u[t] = u;
        g_wv1[t] = v1;
    }
    if (t == 0) {
        float c = wqr_b[0];
#pragma unroll
        for (int k = 0; k < EMB; k++)
            c += wqa_b[k] * wqr_w[k] + wqact_b[k] * wqr_w[EMB + k];
        g_cconst = c;
    }
}

// ---------------- K3: xp1 = (relu(features*ws_w + cvec)) @ wnp_w, packed ----------------
__global__ void build_xp1_kernel(const float* __restrict__ features,
                                 const float* __restrict__ ws_w,
                                 const float* __restrict__ wnp_w) {
    int jp = blockIdx.x * blockDim.x + threadIdx.x;
    if (jp >= NN / 2) return;
    float f0 = features[2 * jp], f1 = features[2 * jp + 1];
    float e0[EMB], e1[EMB];
#pragma unroll
    for (int k = 0; k < EMB; k++) {
        float wk = ws_w[k], ck = g_cvec[k];
        e0[k] = fmaxf(fmaf(f0, wk, ck), 0.f);
        e1[k] = fmaxf(fmaf(f1, wk, ck), 0.f);
    }
    float2* out = reinterpret_cast<float2*>(g_xp_a);
#pragma unroll
    for (int k = 0; k < EMB; k++) {
        float x0 = 0.f, x1 = 0.f;
#pragma unroll
        for (int m = 0; m < EMB; m++) {
            float wm = wnp_w[m * EMB + k];
            x0 = fmaf(e0[m], wm, x0);
            x1 = fmaf(e1[m], wm, x1);
        }
        out[k * (NN / 2) + jp] = make_float2(x0, x1);
    }
}

// ---------------- K4/K6: big pass  emb_out = relu(base + A @ xp_in) ----------------
// 16 rows per block, 2 rows per lane (rq and rq+8), sub = lane&3 owns a 16B
// sub-chunk. A is loaded straight from global with a 1-deep register pipeline
// (next iteration's 4 LDG.128s issue before current FMAs). X' (10 planes) is
// L1/L2-resident; its 10 loads are amortized over 2 rows' worth of FMAs.
// mode 0: read g_xp_a, write packed xp2 into g_xp_b (fused emb @ wnp_w)
// mode 1: read g_xp_b, write embeddings to emb_out and colsum partials
__global__ void __launch_bounds__(256, 2)
big_pass_kernel(const float* __restrict__ A,
                const float* __restrict__ features,
                const float* __restrict__ ws_w,
                const float* __restrict__ wnp_w,
                float* __restrict__ emb_out,
                int mode) {
    __shared__ float red[8 * RB * EMB + RB * EMB];   // 1280 partials + 160 emb

    const int t   = threadIdx.x;
    const int w   = t >> 5;
    const int ln  = t & 31;
    const int rq  = ln >> 2;           // 0..7 (rows rq and rq+8)
    const int sub = ln & 3;            // 0..3 (16B sub-chunk)
    const int i0  = blockIdx.x * RB;
    const float* xp_in = (mode == 0) ? g_xp_a : g_xp_b;
    const ulonglong2* __restrict__ Xq = reinterpret_cast<const ulonglong2*>(xp_in);

    const ulonglong2* __restrict__ A0 =
        reinterpret_cast<const ulonglong2*>(A + (size_t)(i0 + rq) * NN) + sub;
    const ulonglong2* __restrict__ A1 =
        reinterpret_cast<const ulonglong2*>(A + (size_t)(i0 + 8 + rq) * NN) + sub;

    unsigned long long acc0[EMB], acc1[EMB];
#pragma unroll
    for (int k = 0; k < EMB; k++) { acc0[k] = 0ull; acc1[k] = 0ull; }

    // prologue: chunk c = w (always < NCH since w < 8)
    int c = w;
    ulonglong2 a0c = A0[(size_t)c * 4];
    ulonglong2 a1c = A1[(size_t)c * 4];

    const int NIT = (NCH + 7) / 8;     // 79
#pragma unroll 1
    for (int it = 0; it < NIT; ++it) {
        const int cn = c + 8;
        const bool actn = (cn < NCH);
        // prefetch next A chunk (4 independent DRAM LDG.128s, predicated)
        ulonglong2 a0n = a0c, a1n = a1c;
        if (actn) {
            a0n = A0[(size_t)cn * 4];
            a1n = A1[(size_t)cn * 4];
        }

        if (c < NCH) {
            // X for current chunk (L1 hits); 10 independent LDG.128s
            const ulonglong2* xp = Xq + (size_t)c * 4 + sub;
            ulonglong2 xv[EMB];
#pragma unroll
            for (int k = 0; k < EMB; k++) xv[k] = xp[(size_t)k * (NN / 4)];
#pragma unroll
            for (int k = 0; k < EMB; k++) {
                FMA2(acc0[k], a0c.x, xv[k].x);
                FMA2(acc0[k], a0c.y, xv[k].y);
                FMA2(acc1[k], a1c.x, xv[k].x);
                FMA2(acc1[k], a1c.y, xv[k].y);
            }
        }
        a0c = a0n; a1c = a1n; c = cn;
    }

    // combine lo/hi, reduce across the 4 sub-lanes of each row-quad
#pragma unroll
    for (int k = 0; k < EMB; k++) {
        float v0 = lo32(acc0[k]) + hi32(acc0[k]);
        float v1 = lo32(acc1[k]) + hi32(acc1[k]);
        v0 += __shfl_down_sync(0xffffffffu, v0, 2, 4);
        v0 += __shfl_down_sync(0xffffffffu, v0, 1, 4);
        v1 += __shfl_down_sync(0xffffffffu, v1, 2, 4);
        v1 += __shfl_down_sync(0xffffffffu, v1, 1, 4);
        if (sub == 0) {
            red[(w * RB + rq) * EMB + k]     = v0;
            red[(w * RB + 8 + rq) * EMB + k] = v1;
        }
    }
    __syncthreads();

    float* emb_stage = red + 8 * RB * EMB;  // +1280
    if (t < RB * EMB) {                 // 160 threads: one per (row, k)
        int r = t / EMB, k = t - r * EMB;
        float sum = 0.f;
#pragma unroll
        for (int ww = 0; ww < 8; ww++) sum += red[(ww * RB + r) * EMB + k];
        int i = i0 + r;
        float e = fmaf(features[i], ws_w[k], g_cvec[k] + sum);
        e = fmaxf(e, 0.f);
        emb_stage[r * EMB + k] = e;
        if (mode == 1) emb_out[(size_t)i * EMB + k] = e;
    }
    __syncthreads();

    if (mode == 0) {
        if (t < (RB / 2) * EMB) {       // 80 threads: fused xp2 = emb @ wnp_w
            int jpl = t / EMB, k = t - jpl * EMB;
            const float* er0 = &emb_stage[(2 * jpl) * EMB];
            const float* er1 = &emb_stage[(2 * jpl + 1) * EMB];
            float x0 = 0.f, x1 = 0.f;
#pragma unroll
            for (int m = 0; m < EMB; m++) {
                float wm = wnp_w[m * EMB + k];
                x0 = fmaf(er0[m], wm, x0);
                x1 = fmaf(er1[m], wm, x1);
            }
            reinterpret_cast<float2*>(g_xp_b)[k * (NN / 2) + (i0 / 2 + jpl)] =
                make_float2(x0, x1);
        }
    } else {
        if (t < EMB) {                  // per-block column-sum partial
            float sc = 0.f;
#pragma unroll
            for (int r = 0; r < RB; r++) sc += emb_stage[r * EMB + t];
            g_cs_part[blockIdx.x * EMB + t] = sc;
        }
    }
}

// ---------------- K7: colsum reduce + c0  (625 partials = 25 x 25) ----------------
__global__ void colsum_final_kernel() {
    __shared__ float part[25 * EMB];
    __shared__ float csum[EMB];
    int t = threadIdx.x;
    if (t < 25 * EMB) {
        int q = t / EMB, k = t - q * EMB;
        float s = 0.f;
        for (int j = 0; j < 25; j++)
            s += g_cs_part[(q * 25 + j) * EMB + k];
        part[t] = s;
    }
    __syncthreads();
    if (t < EMB) {
        float s = 0.f;
#pragma unroll
        for (int q = 0; q < 25; q++) s += part[q * EMB + t];
        csum[t] = s;
    }
    __syncthreads();
    if (t == 0) {
        float c = g_cconst;
#pragma unroll
        for (int m = 0; m < EMB; m++) c = fmaf(csum[m], g_wv1[m], c);
        g_c0 = c;
    }
}

// ---------------- K8: q_vals = emb3 . u + c0 ----------------
__global__ void qvals_kernel(float* __restrict__ out) {
    int i = blockIdx.x * blockDim.x + threadIdx.x;
    if (i >= NN) return;
    const float* e = out + NN + (size_t)i * EMB;
    float q = g_c0;
#pragma unroll
    for (int k = 0; k < EMB; k++) q = fmaf(e[k], g_u[k], q);
    out[i] = q;
}

// ---------------- launch ----------------
extern "C" void kernel_launch(void* const* d_in, const int* in_sizes, int n_in,
                              void* d_out, int out_size) {
    (void)in_sizes; (void)n_in; (void)out_size;
    const float* features = (const float*)d_in[0];
    const float* weights  = (const float*)d_in[1];
    const float* A        = (const float*)d_in[2];
    const float* ws_w     = (const float*)d_in[3];
    const float* ws_b     = (const float*)d_in[4];
    const float* wnp_w    = (const float*)d_in[5];
    const float* wnp_b    = (const float*)d_in[6];
    const float* wnw_w    = (const float*)d_in[7];
    const float* wnw_b    = (const float*)d_in[8];
    const float* wew_w    = (const float*)d_in[9];
    const float* wew_b    = (const float*)d_in[10];
    const float* wqr_w    = (const float*)d_in[11];
    const float* wqr_b    = (const float*)d_in[12];
    const float* wqa_w    = (const float*)d_in[13];
    const float* wqa_b    = (const float*)d_in[14];
    const float* wqact_w  = (const float*)d_in[15];
    const float* wqact_b  = (const float*)d_in[16];
    float* out = (float*)d_out;

    edge_reduce_kernel<<<ERB, 256>>>(weights, wew_w, wew_b);
    finalize_small_kernel<<<1, 32>>>(ws_b, wnw_w, wnw_b, wnp_b, wqr_w, wqr_b,
                                     wqa_w, wqa_b, wqact_w, wqact_b);
    build_xp1_kernel<<<(NN / 2 + 127) / 128, 128>>>(features, ws_w, wnp_w);
    // iteration 2: emb1 (implicit) -> xp2
    big_pass_kernel<<<BIGB, 256>>>(A, features, ws_w, wnp_w, nullptr, 0);
    // iteration 3: -> embeddings written straight to d_out[N..], + colsum partials
    big_pass_kernel<<<BIGB, 256>>>(A, features, ws_w, wnp_w, out + NN, 1);
    colsum_final_kernel<<<1, 256>>>();
    qvals_kernel<<<(NN + 255) / 256, 256>>>(out);
}

// round 13
// speedup vs baseline: 1.0735x; 1.0735x over previous
#include <cuda_runtime.h>
#include <cstdint>

// Problem constants
#define NN    10000
#define EMB   10
#define EE    160000
#define ERB   200          // edge-reduction blocks
#define RB    16           // rows per big-pass block (2 per lane)
#define BIGB  (NN / RB)    // 625 big-pass blocks
#define NCH   625          // 16-float chunks per row (10000/16)
#define DST   4            // cp.async pipeline depth (stages)

// ---------------- device scratch (no allocations allowed) ----------------
__device__ float g_xp_a[NN * EMB];        // packed X' ping  (plane-k, j-pair float2)
__device__ float g_xp_b[NN * EMB];        // packed X' pong
__device__ float g_edge_part[ERB * EMB];
__device__ float g_cs_part[BIGB * EMB];
__device__ float g_cvec[EMB];             // ws_b + v_weights + wnp_b
__device__ float g_u[EMB];                // wqact_w @ wqr2
__device__ float g_wv1[EMB];              // wqa_w @ wqr1
__device__ float g_cconst;
__device__ float g_c0;

// packed f32x2 FMA (sm_100+): acc.{lo,hi} += a.{lo,hi} * b.{lo,hi}
#define FMA2(acc, a, b) \
    asm("fma.rn.f32x2 %0, %1, %2, %0;" : "+l"(acc) : "l"(a), "l"(b))

#define CP_ASYNC16(smem_u32, gptr) \
    asm volatile("cp.async.cg.shared.global [%0], [%1], 16;" \
                 :: "r"(smem_u32), "l"(gptr) : "memory")
#define CP_COMMIT() \
    asm volatile("cp.async.commit_group;" ::: "memory")
#define CP_WAIT(n) \
    asm volatile("cp.async.wait_group %0;" :: "n"(n) : "memory")

__device__ __forceinline__ float lo32(unsigned long long v) {
    return __uint_as_float((unsigned int)v);
}
__device__ __forceinline__ float hi32(unsigned long long v) {
    return __uint_as_float((unsigned int)(v >> 32));
}

// ---------------- K1: edge embedding partial reduction ----------------
__global__ void edge_reduce_kernel(const float* __restrict__ w,
                                   const float* __restrict__ wew_w,
                                   const float* __restrict__ wew_b) {
    float a[EMB], b[EMB], s[EMB];
#pragma unroll
    for (int k = 0; k < EMB; k++) { a[k] = wew_w[k]; b[k] = wew_b[k]; s[k] = 0.f; }

    for (int e = blockIdx.x * blockDim.x + threadIdx.x; e < EE;
         e += gridDim.x * blockDim.x) {
        float we = w[e];
#pragma unroll
        for (int k = 0; k < EMB; k++)
            s[k] += fmaxf(fmaf(we, a[k], b[k]), 0.f);
    }
#pragma unroll
    for (int k = 0; k < EMB; k++)
        for (int off = 16; off; off >>= 1)
            s[k] += __shfl_down_sync(0xffffffffu, s[k], off);

    __shared__ float red[8 * EMB];
    int t = threadIdx.x, lane = t & 31, wrp = t >> 5;
    if (lane == 0) {
#pragma unroll
        for (int k = 0; k < EMB; k++) red[wrp * EMB + k] = s[k];
    }
    __syncthreads();
    if (t < EMB) {
        float tot = 0.f;
#pragma unroll
        for (int ww = 0; ww < 8; ww++) tot += red[ww * EMB + t];
        g_edge_part[blockIdx.x * EMB + t] = tot;
    }
}

// ---------------- K2: finalize small vectors ----------------
__global__ void finalize_small_kernel(const float* __restrict__ ws_b,
                                      const float* __restrict__ wnw_w,
                                      const float* __restrict__ wnw_b,
                                      const float* __restrict__ wnp_b,
                                      const float* __restrict__ wqr_w,
                                      const float* __restrict__ wqr_b,
                                      const float* __restrict__ wqa_w,
                                      const float* __restrict__ wqa_b,
                                      const float* __restrict__ wqact_w,
                                      const float* __restrict__ wqact_b) {
    __shared__ float s[EMB];
    int t = threadIdx.x;
    if (t < EMB) {
        float acc = 0.f;
        for (int b2 = 0; b2 < ERB; b2++) acc += g_edge_part[b2 * EMB + t];
        s[t] = acc;
    }
    __syncthreads();
    if (t < EMB) {
        float vw = wnw_b[t];
#pragma unroll
        for (int m = 0; m < EMB; m++) vw = fmaf(s[m], wnw_w[m * EMB + t], vw);
        g_cvec[t] = ws_b[t] + vw + wnp_b[t];

        float u = 0.f, v1 = 0.f;
#pragma unroll
        for (int k = 0; k < EMB; k++) {
            u  = fmaf(wqact_w[t * EMB + k], wqr_w[EMB + k], u);
            v1 = fmaf(wqa_w[t * EMB + k],   wqr_w[k],       v1);
        }
        g_u[t] = u;
        g_wv1[t] = v1;
    }
    if (t == 0) {
        float c = wqr_b[0];
#pragma unroll
        for (int k = 0; k < EMB; k++)
            c += wqa_b[k] * wqr_w[k] + wqact_b[k] * wqr_w[EMB + k];
        g_cconst = c;
    }
}

// ---------------- K3: xp1 = (relu(features*ws_w + cvec)) @ wnp_w, packed ----------------
__global__ void build_xp1_kernel(const float* __restrict__ features,
                                 const float* __restrict__ ws_w,
                                 const float* __restrict__ wnp_w) {
    int jp = blockIdx.x * blockDim.x + threadIdx.x;
    if (jp >= NN / 2) return;
    float f0 = features[2 * jp], f1 = features[2 * jp + 1];
    float e0[EMB], e1[EMB];
#pragma unroll
    for (int k = 0; k < EMB; k++) {
        float wk = ws_w[k], ck = g_cvec[k];
        e0[k] = fmaxf(fmaf(f0, wk, ck), 0.f);
        e1[k] = fmaxf(fmaf(f1, wk, ck), 0.f);
    }
    float2* out = reinterpret_cast<float2*>(g_xp_a);
#pragma unroll
    for (int k = 0; k < EMB; k++) {
        float x0 = 0.f, x1 = 0.f;
#pragma unroll
        for (int m = 0; m < EMB; m++) {
            float wm = wnp_w[m * EMB + k];
            x0 = fmaf(e0[m], wm, x0);
            x1 = fmaf(e1[m], wm, x1);
        }
        out[k * (NN / 2) + jp] = make_float2(x0, x1);
    }
}

// ---------------- K4/K6: big pass  emb_out = relu(base + A @ xp_in) ----------------
// Warp-private cp.async pipeline + 2 rows per lane:
//   lane ln: rq = ln>>2 owns rows (i0+rq) and (i0+8+rq), sub = ln&3 is its
//   16B sub-chunk. Each stage holds 1KB (row rq half at +0, row rq+8 half at
//   +512). The 10 X'-plane loads per chunk feed 80 FMA2 (amortized 2x vs R11).
//   No block barriers in the mainloop; per-warp ring, wait_group + syncwarp.
// mode 0: read g_xp_a, write packed xp2 into g_xp_b (fused emb @ wnp_w)
// mode 1: read g_xp_b, write embeddings to emb_out and colsum partials
__global__ void __launch_bounds__(256, 2)
big_pass_kernel(const float* __restrict__ A,
                const float* __restrict__ features,
                const float* __restrict__ ws_w,
                const float* __restrict__ wnp_w,
                float* __restrict__ emb_out,
                int mode) {
    __shared__ __align__(16) char stage[8][DST][1024];   // 32KB warp-private rings
    __shared__ float red[8 * RB * EMB + RB * EMB];       // 1280 partials + 160 emb

    const int t   = threadIdx.x;
    const int w   = t >> 5;
    const int ln  = t & 31;
    const int rq  = ln >> 2;           // 0..7 (rows rq and rq+8)
    const int sub = ln & 3;            // 0..3 (16B sub-chunk)
    const int i0  = blockIdx.x * RB;
    const float* xp_in = (mode == 0) ? g_xp_a : g_xp_b;
    const ulonglong2* __restrict__ Xq = reinterpret_cast<const ulonglong2*>(xp_in);

    // global bases for this lane's two rows, at its 16B sub-offset
    const char* ab0 = reinterpret_cast<const char*>(
        A + (size_t)(i0 + rq) * NN + sub * 4);
    const char* ab1 = reinterpret_cast<const char*>(
        A + (size_t)(i0 + 8 + rq) * NN + sub * 4);
    // this lane's 16B slots in its warp's ring (stage s at +s*1024)
    unsigned int sb0 =
        (unsigned int)__cvta_generic_to_shared(&stage[w][0][0]) + ln * 16;
    unsigned int sb1 = sb0 + 512;

    unsigned long long acc0[EMB], acc1[EMB];
#pragma unroll
    for (int k = 0; k < EMB; k++) { acc0[k] = 0ull; acc1[k] = 0ull; }

    // prologue: fill DST-1 stages (chunk c = w + 8*s; 64B per row per chunk)
#pragma unroll
    for (int s = 0; s < DST - 1; ++s) {
        int c = w + 8 * s;
        if (c < NCH) {
            CP_ASYNC16(sb0 + s * 1024, ab0 + (size_t)c * 64);
            CP_ASYNC16(sb1 + s * 1024, ab1 + (size_t)c * 64);
        }
        CP_COMMIT();
    }

    const int NIT = (NCH + 7) / 8;     // 79 (uniform across warps; guarded)
#pragma unroll 1
    for (int it = 0; it < NIT; ++it) {
        const int c = w + 8 * it;
        const bool act = (c < NCH);

        // X prefetch (independent of A data) — issues before the wait below
        ulonglong2 xv[EMB];
        if (act) {
            const ulonglong2* xp = Xq + (size_t)c * 4 + sub;
#pragma unroll
            for (int k = 0; k < EMB; k++) xv[k] = xp[(size_t)k * (NN / 4)];
        }

        CP_WAIT(DST - 2);
        __syncwarp();

        if (act) {
            const ulonglong2* sp = reinterpret_cast<const ulonglong2*>(
                &stage[w][it % DST][0]);
            ulonglong2 a0 = sp[ln];
            ulonglong2 a1 = sp[ln + 32];
#pragma unroll
            for (int k = 0; k < EMB; k++) {
                FMA2(acc0[k], a0.x, xv[k].x);
                FMA2(acc0[k], a0.y, xv[k].y);
                FMA2(acc1[k], a1.x, xv[k].x);
                FMA2(acc1[k], a1.y, xv[k].y);
            }
        }
        __syncwarp();

        // refill the stage consumed last iteration
        int cr = w + 8 * (it + DST - 1);
        if (cr < NCH) {
            int sl = (it + DST - 1) % DST;
            CP_ASYNC16(sb0 + sl * 1024, ab0 + (size_t)cr * 64);
            CP_ASYNC16(sb1 + sl * 1024, ab1 + (size_t)cr * 64);
        }
        CP_COMMIT();
    }

    CP_WAIT(0);

    // combine lo/hi, reduce across the 4 sub-lanes of each row-quad
#pragma unroll
    for (int k = 0; k < EMB; k++) {
        float v0 = lo32(acc0[k]) + hi32(acc0[k]);
        float v1 = lo32(acc1[k]) + hi32(acc1[k]);
        v0 += __shfl_down_sync(0xffffffffu, v0, 2, 4);
        v0 += __shfl_down_sync(0xffffffffu, v0, 1, 4);
        v1 += __shfl_down_sync(0xffffffffu, v1, 2, 4);
        v1 += __shfl_down_sync(0xffffffffu, v1, 1, 4);
        if (sub == 0) {
            red[(w * RB + rq) * EMB + k]     = v0;
            red[(w * RB + 8 + rq) * EMB + k] = v1;
        }
    }
    __syncthreads();

    float* emb_stage = red + 8 * RB * EMB;  // +1280
    if (t < RB * EMB) {                 // 160 threads: one per (row, k)
        int r = t / EMB, k = t - r * EMB;
        float sum = 0.f;
#pragma unroll
        for (int ww = 0; ww < 8; ww++) sum += red[(ww * RB + r) * EMB + k];
        int i = i0 + r;
        float e = fmaf(features[i], ws_w[k], g_cvec[k] + sum);
        e = fmaxf(e, 0.f);
        emb_stage[r * EMB + k] = e;
        if (mode == 1) emb_out[(size_t)i * EMB + k] = e;
    }
    __syncthreads();

    if (mode == 0) {
        if (t < (RB / 2) * EMB) {       // 80 threads: fused xp2 = emb @ wnp_w
            int jpl = t / EMB, k = t - jpl * EMB;
            const float* er0 = &emb_stage[(2 * jpl) * EMB];
            const float* er1 = &emb_stage[(2 * jpl + 1) * EMB];
            float x0 = 0.f, x1 = 0.f;
#pragma unroll
            for (int m = 0; m < EMB; m++) {
                float wm = wnp_w[m * EMB + k];
                x0 = fmaf(er0[m], wm, x0);
                x1 = fmaf(er1[m], wm, x1);
            }
            reinterpret_cast<float2*>(g_xp_b)[k * (NN / 2) + (i0 / 2 + jpl)] =
                make_float2(x0, x1);
        }
    } else {
        if (t < EMB) {                  // per-block column-sum partial
            float sc = 0.f;
#pragma unroll
            for (int r = 0; r < RB; r++) sc += emb_stage[r * EMB + t];
            g_cs_part[blockIdx.x * EMB + t] = sc;
        }
    }
}

// ---------------- K7: colsum reduce + c0  (625 partials = 25 x 25) ----------------
__global__ void colsum_final_kernel() {
    __shared__ float part[25 * EMB];
    __shared__ float csum[EMB];
    int t = threadIdx.x;
    if (t < 25 * EMB) {
        int q = t / EMB, k = t - q * EMB;
        float s = 0.f;
        for (int j = 0; j < 25; j++)
            s += g_cs_part[(q * 25 + j) * EMB + k];
        part[t] = s;
    }
    __syncthreads();
    if (t < EMB) {
        float s = 0.f;
#pragma unroll
        for (int q = 0; q < 25; q++) s += part[q * EMB + t];
        csum[t] = s;
    }
    __syncthreads();
    if (t == 0) {
        float c = g_cconst;
#pragma unroll
        for (int m = 0; m < EMB; m++) c = fmaf(csum[m], g_wv1[m], c);
        g_c0 = c;
    }
}

// ---------------- K8: q_vals = emb3 . u + c0 ----------------
__global__ void qvals_kernel(float* __restrict__ out) {
    int i = blockIdx.x * blockDim.x + threadIdx.x;
    if (i >= NN) return;
    const float* e = out + NN + (size_t)i * EMB;
    float q = g_c0;
#pragma unroll
    for (int k = 0; k < EMB; k++) q = fmaf(e[k], g_u[k], q);
    out[i] = q;
}

// ---------------- launch ----------------
extern "C" void kernel_launch(void* const* d_in, const int* in_sizes, int n_in,
                              void* d_out, int out_size) {
    (void)in_sizes; (void)n_in; (void)out_size;
    const float* features = (const float*)d_in[0];
    const float* weights  = (const float*)d_in[1];
    const float* A        = (const float*)d_in[2];
    const float* ws_w     = (const float*)d_in[3];
    const float* ws_b     = (const float*)d_in[4];
    const float* wnp_w    = (const float*)d_in[5];
    const float* wnp_b    = (const float*)d_in[6];
    const float* wnw_w    = (const float*)d_in[7];
    const float* wnw_b    = (const float*)d_in[8];
    const float* wew_w    = (const float*)d_in[9];
    const float* wew_b    = (const float*)d_in[10];
    const float* wqr_w    = (const float*)d_in[11];
    const float* wqr_b    = (const float*)d_in[12];
    const float* wqa_w    = (const float*)d_in[13];
    const float* wqa_b    = (const float*)d_in[14];
    const float* wqact_w  = (const float*)d_in[15];
    const float* wqact_b  = (const float*)d_in[16];
    float* out = (float*)d_out;

    edge_reduce_kernel<<<ERB, 256>>>(weights, wew_w, wew_b);
    finalize_small_kernel<<<1, 32>>>(ws_b, wnw_w, wnw_b, wnp_b, wqr_w, wqr_b,
                                     wqa_w, wqa_b, wqact_w, wqact_b);
    build_xp1_kernel<<<(NN / 2 + 127) / 128, 128>>>(features, ws_w, wnp_w);
    // iteration 2: emb1 (implicit) -> xp2
    big_pass_kernel<<<BIGB, 256>>>(A, features, ws_w, wnp_w, nullptr, 0);
    // iteration 3: -> embeddings written straight to d_out[N..], + colsum partials
    big_pass_kernel<<<BIGB, 256>>>(A, features, ws_w, wnp_w, out + NN, 1);
    colsum_final_kernel<<<1, 256>>>();
    qvals_kernel<<<(NN + 255) / 256, 256>>>(out);
}

// round 14
// speedup vs baseline: 1.1272x; 1.0501x over previous
#include <cuda_runtime.h>
#include <cstdint>

// Problem constants
#define NN    10000
#define EMB   10
#define EE    160000
#define ERB   200          // edge-reduction blocks
#define RB    8            // rows per big-pass block
#define BIGB  (NN / RB)    // 1250 big-pass blocks
#define NCH   625          // 16-float chunks per row (10000/16)
#define DST   6            // cp.async pipeline depth (stages)

// ---------------- device scratch (no allocations allowed) ----------------
__device__ float g_xp_a[NN * EMB];        // packed X' ping  (plane-k, j-pair float2)
__device__ float g_xp_b[NN * EMB];        // packed X' pong
__device__ float g_edge_part[ERB * EMB];
__device__ float g_cs_part[BIGB * EMB];
__device__ float g_cvec[EMB];             // ws_b + v_weights + wnp_b
__device__ float g_u[EMB];                // wqact_w @ wqr2
__device__ float g_wv1[EMB];              // wqa_w @ wqr1
__device__ float g_cconst;
__device__ float g_c0;

// packed f32x2 FMA (sm_100+): acc.{lo,hi} += a.{lo,hi} * b.{lo,hi}
#define FMA2(acc, a, b) \
    asm("fma.rn.f32x2 %0, %1, %2, %0;" : "+l"(acc) : "l"(a), "l"(b))

#define CP_ASYNC16(smem_u32, gptr) \
    asm volatile("cp.async.cg.shared.global [%0], [%1], 16;" \
                 :: "r"(smem_u32), "l"(gptr) : "memory")
#define CP_COMMIT() \
    asm volatile("cp.async.commit_group;" ::: "memory")
#define CP_WAIT(n) \
    asm volatile("cp.async.wait_group %0;" :: "n"(n) : "memory")

__device__ __forceinline__ float lo32(unsigned long long v) {
    return __uint_as_float((unsigned int)v);
}
__device__ __forceinline__ float hi32(unsigned long long v) {
    return __uint_as_float((unsigned int)(v >> 32));
}

// ---------------- K1: edge embedding partial reduction ----------------
__global__ void edge_reduce_kernel(const float* __restrict__ w,
                                   const float* __restrict__ wew_w,
                                   const float* __restrict__ wew_b) {
    float a[EMB], b[EMB], s[EMB];
#pragma unroll
    for (int k = 0; k < EMB; k++) { a[k] = wew_w[k]; b[k] = wew_b[k]; s[k] = 0.f; }

    for (int e = blockIdx.x * blockDim.x + threadIdx.x; e < EE;
         e += gridDim.x * blockDim.x) {
        float we = w[e];
#pragma unroll
        for (int k = 0; k < EMB; k++)
            s[k] += fmaxf(fmaf(we, a[k], b[k]), 0.f);
    }
#pragma unroll
    for (int k = 0; k < EMB; k++)
        for (int off = 16; off; off >>= 1)
            s[k] += __shfl_down_sync(0xffffffffu, s[k], off);

    __shared__ float red[8 * EMB];
    int t = threadIdx.x, lane = t & 31, wrp = t >> 5;
    if (lane == 0) {
#pragma unroll
        for (int k = 0; k < EMB; k++) red[wrp * EMB + k] = s[k];
    }
    __syncthreads();
    if (t < EMB) {
        float tot = 0.f;
#pragma unroll
        for (int ww = 0; ww < 8; ww++) tot += red[ww * EMB + t];
        g_edge_part[blockIdx.x * EMB + t] = tot;
    }
}

// ---------------- K2: finalize small vectors ----------------
__global__ void finalize_small_kernel(const float* __restrict__ ws_b,
                                      const float* __restrict__ wnw_w,
                                      const float* __restrict__ wnw_b,
                                      const float* __restrict__ wnp_b,
                                      const float* __restrict__ wqr_w,
                                      const float* __restrict__ wqr_b,
                                      const float* __restrict__ wqa_w,
                                      const float* __restrict__ wqa_b,
                                      const float* __restrict__ wqact_w,
                                      const float* __restrict__ wqact_b) {
    __shared__ float s[EMB];
    int t = threadIdx.x;
    if (t < EMB) {
        float acc = 0.f;
        for (int b2 = 0; b2 < ERB; b2++) acc += g_edge_part[b2 * EMB + t];
        s[t] = acc;
    }
    __syncthreads();
    if (t < EMB) {
        float vw = wnw_b[t];
#pragma unroll
        for (int m = 0; m < EMB; m++) vw = fmaf(s[m], wnw_w[m * EMB + t], vw);
        g_cvec[t] = ws_b[t] + vw + wnp_b[t];

        float u = 0.f, v1 = 0.f;
#pragma unroll
        for (int k = 0; k < EMB; k++) {
            u  = fmaf(wqact_w[t * EMB + k], wqr_w[EMB + k], u);
            v1 = fmaf(wqa_w[t * EMB + k],   wqr_w[k],       v1);
        }
        g_u[t] = u;
        g_wv1[t] = v1;
    }
    if (t == 0) {
        float c = wqr_b[0];
#pragma unroll
        for (int k = 0; k < EMB; k++)
            c += wqa_b[k] * wqr_w[k] + wqact_b[k] * wqr_w[EMB + k];
        g_cconst = c;
    }
}

// ---------------- K3: xp1 = (relu(features*ws_w + cvec)) @ wnp_w, packed ----------------
__global__ void build_xp1_kernel(const float* __restrict__ features,
                                 const float* __restrict__ ws_w,
                                 const float* __restrict__ wnp_w) {
    int jp = blockIdx.x * blockDim.x + threadIdx.x;
    if (jp >= NN / 2) return;
    float f0 = features[2 * jp], f1 = features[2 * jp + 1];
    float e0[EMB], e1[EMB];
#pragma unroll
    for (int k = 0; k < EMB; k++) {
        float wk = ws_w[k], ck = g_cvec[k];
        e0[k] = fmaxf(fmaf(f0, wk, ck), 0.f);
        e1[k] = fmaxf(fmaf(f1, wk, ck), 0.f);
    }
    float2* out = reinterpret_cast<float2*>(g_xp_a);
#pragma unroll
    for (int k = 0; k < EMB; k++) {
        float x0 = 0.f, x1 = 0.f;
#pragma unroll
        for (int m = 0; m < EMB; m++) {
            float wm = wnp_w[m * EMB + k];
            x0 = fmaf(e0[m], wm, x0);
            x1 = fmaf(e1[m], wm, x1);
        }
        out[k * (NN / 2) + jp] = make_float2(x0, x1);
    }
}

// ---------------- K4/K6: big pass  emb_out = relu(base + A @ xp_in) ----------------
// R11 structure (warp-private cp.async ring, 1 row/lane, no block barriers in
// the mainloop) at 3 blocks/SM (24 warps) for latency hiding. DST trimmed to 6
// so smem fits 3 resident blocks; regs capped at 84 by launch bounds (R11
// needed 78, so no spills).
// mode 0: read g_xp_a, write packed xp2 into g_xp_b (fused emb @ wnp_w)
// mode 1: read g_xp_b, write embeddings to emb_out and colsum partials
__global__ void __launch_bounds__(256, 3)
big_pass_kernel(const float* __restrict__ A,
                const float* __restrict__ features,
                const float* __restrict__ ws_w,
                const float* __restrict__ wnp_w,
                float* __restrict__ emb_out,
                int mode) {
    __shared__ __align__(16) char stage[8][DST][512];   // 24KB warp-private rings
    __shared__ float red[8 * RB * EMB + RB * EMB];      // 640 partials + 80 emb

    const int t   = threadIdx.x;
    const int w   = t >> 5;
    const int ln  = t & 31;
    const int row = ln >> 2;           // 0..7
    const int sub = ln & 3;            // 0..3 (16B sub-chunk)
    const int i0  = blockIdx.x * RB;
    const float* xp_in = (mode == 0) ? g_xp_a : g_xp_b;
    const ulonglong2* __restrict__ Xq = reinterpret_cast<const ulonglong2*>(xp_in);

    // global base for this lane's row, at its 16B sub-offset
    const char* abase = reinterpret_cast<const char*>(
        A + (size_t)(i0 + row) * NN + sub * 4);
    // this lane's 16B slot in its warp's ring (stage s at +s*512)
    unsigned int sbase =
        (unsigned int)__cvta_generic_to_shared(&stage[w][0][0]) + ln * 16;

    unsigned long long acc[EMB];
#pragma unroll
    for (int k = 0; k < EMB; k++) acc[k] = 0ull;

    // prologue: fill DST-1 stages (chunk c = w + 8*s; 64B per row per chunk)
#pragma unroll
    for (int s = 0; s < DST - 1; ++s) {
        int c = w + 8 * s;
        if (c < NCH) CP_ASYNC16(sbase + s * 512, abase + (size_t)c * 64);
        CP_COMMIT();
    }

    const int NIT = (NCH + 7) / 8;     // 79 (uniform across warps; guarded)
#pragma unroll 1
    for (int it = 0; it < NIT; ++it) {
        const int c = w + 8 * it;
        const bool act = (c < NCH);

        // X prefetch (independent of A data) — issues before the wait below
        ulonglong2 xv[EMB];
        if (act) {
            const ulonglong2* xp = Xq + (size_t)c * 4 + sub;
#pragma unroll
            for (int k = 0; k < EMB; k++) xv[k] = xp[(size_t)k * (NN / 4)];
        }

        CP_WAIT(DST - 2);
        __syncwarp();

        if (act) {
            const ulonglong2* sp = reinterpret_cast<const ulonglong2*>(
                &stage[w][it % DST][0]);
            ulonglong2 av = sp[ln];
#pragma unroll
            for (int k = 0; k < EMB; k++) {
                FMA2(acc[k], av.x, xv[k].x);
                FMA2(acc[k], av.y, xv[k].y);
            }
        }
        __syncwarp();

        // refill the stage consumed last iteration
        int cr = w + 8 * (it + DST - 1);
        if (cr < NCH)
            CP_ASYNC16(sbase + ((it + DST - 1) % DST) * 512,
                       abase + (size_t)cr * 64);
        CP_COMMIT();
    }

    CP_WAIT(0);

    // reduce over the 4 sub-lanes of each row; leader lane writes partials
#pragma unroll
    for (int k = 0; k < EMB; k++) {
        float v = lo32(acc[k]) + hi32(acc[k]);
        v += __shfl_down_sync(0xffffffffu, v, 2, 4);
        v += __shfl_down_sync(0xffffffffu, v, 1, 4);
        if (sub == 0) red[(w * RB + row) * EMB + k] = v;
    }
    __syncthreads();

    float* emb_stage = red + 8 * RB * EMB;  // +640
    if (t < RB * EMB) {                 // 80 threads: one per (row, k)
        int r = t / EMB, k = t - r * EMB;
        float sum = 0.f;
#pragma unroll
        for (int ww = 0; ww < 8; ww++) sum += red[(ww * RB + r) * EMB + k];
        int i = i0 + r;
        float e = fmaf(features[i], ws_w[k], g_cvec[k] + sum);
        e = fmaxf(e, 0.f);
        emb_stage[r * EMB + k] = e;
        if (mode == 1) emb_out[(size_t)i * EMB + k] = e;
    }
    __syncthreads();

    if (mode == 0) {
        if (t < (RB / 2) * EMB) {       // 40 threads: fused xp2 = emb @ wnp_w
            int jpl = t / EMB, k = t - jpl * EMB;
            const float* er0 = &emb_stage[(2 * jpl) * EMB];
            const float* er1 = &emb_stage[(2 * jpl + 1) * EMB];
            float x0 = 0.f, x1 = 0.f;
#pragma unroll
            for (int m = 0; m < EMB; m++) {
                float wm = wnp_w[m * EMB + k];
                x0 = fmaf(er0[m], wm, x0);
                x1 = fmaf(er1[m], wm, x1);
            }
            reinterpret_cast<float2*>(g_xp_b)[k * (NN / 2) + (i0 / 2 + jpl)] =
                make_float2(x0, x1);
        }
    } else {
        if (t < EMB) {                  // per-block column-sum partial
            float sc = 0.f;
#pragma unroll
            for (int r = 0; r < RB; r++) sc += emb_stage[r * EMB + t];
            g_cs_part[blockIdx.x * EMB + t] = sc;
        }
    }
}

// ---------------- K7: colsum reduce + c0  (1250 partials = 25 x 50) ----------------
__global__ void colsum_final_kernel() {
    __shared__ float part[25 * EMB];
    __shared__ float csum[EMB];
    int t = threadIdx.x;
    if (t < 25 * EMB) {
        int q = t / EMB, k = t - q * EMB;
        float s = 0.f;
        for (int j = 0; j < 50; j++)
            s += g_cs_part[(q * 50 + j) * EMB + k];
        part[t] = s;
    }
    __syncthreads();
    if (t < EMB) {
        float s = 0.f;
#pragma unroll
        for (int q = 0; q < 25; q++) s += part[q * EMB + t];
        csum[t] = s;
    }
    __syncthreads();
    if (t == 0) {
        float c = g_cconst;
#pragma unroll
        for (int m = 0; m < EMB; m++) c = fmaf(csum[m], g_wv1[m], c);
        g_c0 = c;
    }
}

// ---------------- K8: q_vals = emb3 . u + c0 ----------------
__global__ void qvals_kernel(float* __restrict__ out) {
    int i = blockIdx.x * blockDim.x + threadIdx.x;
    if (i >= NN) return;
    const float* e = out + NN + (size_t)i * EMB;
    float q = g_c0;
#pragma unroll
    for (int k = 0; k < EMB; k++) q = fmaf(e[k], g_u[k], q);
    out[i] = q;
}

// ---------------- launch ----------------
extern "C" void kernel_launch(void* const* d_in, const int* in_sizes, int n_in,
                              void* d_out, int out_size) {
    (void)in_sizes; (void)n_in; (void)out_size;
    const float* features = (const float*)d_in[0];
    const float* weights  = (const float*)d_in[1];
    const float* A        = (const float*)d_in[2];
    const float* ws_w     = (const float*)d_in[3];
    const float* ws_b     = (const float*)d_in[4];
    const float* wnp_w    = (const float*)d_in[5];
    const float* wnp_b    = (const float*)d_in[6];
    const float* wnw_w    = (const float*)d_in[7];
    const float* wnw_b    = (const float*)d_in[8];
    const float* wew_w    = (const float*)d_in[9];
    const float* wew_b    = (const float*)d_in[10];
    const float* wqr_w    = (const float*)d_in[11];
    const float* wqr_b    = (const float*)d_in[12];
    const float* wqa_w    = (const float*)d_in[13];
    const float* wqa_b    = (const float*)d_in[14];
    const float* wqact_w  = (const float*)d_in[15];
    const float* wqact_b  = (const float*)d_in[16];
    float* out = (float*)d_out;

    edge_reduce_kernel<<<ERB, 256>>>(weights, wew_w, wew_b);
    finalize_small_kernel<<<1, 32>>>(ws_b, wnw_w, wnw_b, wnp_b, wqr_w, wqr_b,
                                     wqa_w, wqa_b, wqact_w, wqact_b);
    build_xp1_kernel<<<(NN / 2 + 127) / 128, 128>>>(features, ws_w, wnp_w);
    // iteration 2: emb1 (implicit) -> xp2
    big_pass_kernel<<<BIGB, 256>>>(A, features, ws_w, wnp_w, nullptr, 0);
    // iteration 3: -> embeddings written straight to d_out[N..], + colsum partials
    big_pass_kernel<<<BIGB, 256>>>(A, features, ws_w, wnp_w, out + NN, 1);
    colsum_final_kernel<<<1, 256>>>();
    qvals_kernel<<<(NN + 255) / 256, 256>>>(out);
}